// round 1
// baseline (speedup 1.0000x reference)
#include <cuda_runtime.h>

// Problem constants (fixed by the dataset)
#define MAXN 100352
#define MAXE 5000192

// ---- scratch (static device globals; no allocation allowed) ----
__device__ int   g_count[MAXN];
__device__ int   g_rowptr[MAXN + 1];
__device__ int   g_cursor[MAXN];
__device__ int   g_col[MAXE];
__device__ float g_dinv[MAXN];
__device__ float g_z0[MAXN];
__device__ float g_zA[MAXN], g_zB[MAXN];
__device__ float g_yA[MAXN], g_yB[MAXN];
__device__ int   g_is64;

// ---------------------------------------------------------------
// 0) zero counters
__global__ void zero_kernel(int N) {
    int i = blockIdx.x * blockDim.x + threadIdx.x;
    if (i < N) { g_count[i] = 0; g_cursor[i] = 0; }
}

// 1) detect edge dtype: int64 (little-endian) has all-zero high words
__global__ void detect_kernel(const unsigned int* e) {
    if (blockIdx.x == 0 && threadIdx.x == 0) {
        int is64 = 1;
        #pragma unroll 1
        for (int i = 1; i < 1024; i += 2) {
            if (e[i] != 0u) { is64 = 0; break; }
        }
        g_is64 = is64;
    }
}

__device__ __forceinline__ int load_idx(const void* eidx, long long pos) {
    if (g_is64) return (int)((const long long*)eidx)[pos];
    return ((const int*)eidx)[pos];
}

// 2) in-degree histogram over dst
__global__ void hist_kernel(const void* eidx, int E) {
    int e = blockIdx.x * blockDim.x + threadIdx.x;
    if (e >= E) return;
    int d = load_idx(eidx, (long long)E + e);
    atomicAdd(&g_count[d], 1);
}

// 3) single-block exclusive scan of g_count -> g_rowptr  (N ~ 100K, 1024 threads)
__global__ void scan_kernel(int N) {
    __shared__ int sums[1024];
    int t = threadIdx.x;
    int C = (N + 1023) >> 10;
    int beg = t * C;
    int end = min(beg + C, N);
    int s = 0;
    for (int i = beg; i < end; i++) s += g_count[i];
    sums[t] = s;
    __syncthreads();
    // Hillis-Steele inclusive scan
    for (int o = 1; o < 1024; o <<= 1) {
        int v = (t >= o) ? sums[t - o] : 0;
        __syncthreads();
        sums[t] += v;
        __syncthreads();
    }
    int off = (t == 0) ? 0 : sums[t - 1];
    for (int i = beg; i < end; i++) {
        g_rowptr[i] = off;
        off += g_count[i];
    }
    if (t == 1023) g_rowptr[N] = sums[1023];
}

// 4) dinv = rsqrt(in-degree + 1)   (self loop)
__global__ void dinv_kernel(int N) {
    int i = blockIdx.x * blockDim.x + threadIdx.x;
    if (i < N) g_dinv[i] = rsqrtf((float)g_count[i] + 1.0f);
}

// 5) CSR placement: col[rowptr[dst] + cursor[dst]++] = src
__global__ void place_kernel(const void* eidx, int E) {
    int e = blockIdx.x * blockDim.x + threadIdx.x;
    if (e >= E) return;
    int s = load_idx(eidx, e);
    int d = load_idx(eidx, (long long)E + e);
    int idx = g_rowptr[d] + atomicAdd(&g_cursor[d], 1);
    g_col[idx] = s;
}

// 6) MLP encoder collapsed to scalar: z0 = relu(relu(x*W1+b1)@W2+b2) @ W3
__global__ void encoder_kernel(const float* __restrict__ x,
                               const float* __restrict__ W1, const float* __restrict__ b1,
                               const float* __restrict__ W2, const float* __restrict__ b2,
                               const float* __restrict__ W3, int N) {
    __shared__ float sW2[256], sW1[16], sb1[16], sb2[16], sW3[16];
    int t = threadIdx.x;
    if (t < 256) sW2[t] = W2[t];
    if (t < 16) { sW1[t] = W1[t]; sb1[t] = b1[t]; sb2[t] = b2[t]; sW3[t] = W3[t]; }
    __syncthreads();
    int i = blockIdx.x * blockDim.x + t;
    if (i >= N) return;
    float xv = x[i];
    float h1[16];
    #pragma unroll
    for (int j = 0; j < 16; j++) h1[j] = fmaxf(xv * sW1[j] + sb1[j], 0.0f);
    float z = 0.0f;
    #pragma unroll
    for (int j = 0; j < 16; j++) {
        float a = sb2[j];
        #pragma unroll
        for (int k = 0; k < 16; k++) a = fmaf(h1[k], sW2[k * 16 + j], a);
        z = fmaf(fmaxf(a, 0.0f), sW3[j], z);
    }
    float di = g_dinv[i];
    g_z0[i] = z;
    g_zA[i] = z;
    g_yA[i] = di * z;   // y = dinv * z
}

// 7) one APPNP step on scalars:
//    agg_i = dinv_i * sum_{e in row i} y[col[e]]  +  dinv_i^2 * z_i   (self loop)
//    z'    = 0.9*agg + 0.1*z0 ;  y' = dinv * z'
// warp per row
__global__ void prop_kernel(int flag, int N) {
    const float* __restrict__ yin = flag ? g_yB : g_yA;
    const float* __restrict__ zin = flag ? g_zB : g_zA;
    float* zout = flag ? g_zA : g_zB;
    float* yout = flag ? g_yA : g_yB;

    int gw = (blockIdx.x * blockDim.x + threadIdx.x) >> 5;
    int lane = threadIdx.x & 31;
    if (gw >= N) return;
    int beg = g_rowptr[gw];
    int end = g_rowptr[gw + 1];
    float s = 0.0f;
    for (int e = beg + lane; e < end; e += 32) s += __ldg(&yin[g_col[e]]);
    #pragma unroll
    for (int o = 16; o; o >>= 1) s += __shfl_xor_sync(0xffffffffu, s, o);
    if (lane == 0) {
        float di = g_dinv[gw];
        float agg = fmaf(di, s, di * di * zin[gw]);
        float zn = fmaf(0.9f, agg, 0.1f * g_z0[gw]);
        zout[gw] = zn;
        yout[gw] = di * zn;
    }
}

// 8) out = z_final + b3
__global__ void final_kernel(const float* __restrict__ b3, float* __restrict__ out, int N) {
    int i = blockIdx.x * blockDim.x + threadIdx.x;
    if (i < N) out[i] = g_zA[i] + b3[0];
}

extern "C" void kernel_launch(void* const* d_in, const int* in_sizes, int n_in,
                              void* d_out, int out_size) {
    const float* x  = (const float*)d_in[0];
    const void*  ei = d_in[1];
    const float* W1 = (const float*)d_in[2];
    const float* b1 = (const float*)d_in[3];
    const float* W2 = (const float*)d_in[4];
    const float* b2 = (const float*)d_in[5];
    const float* W3 = (const float*)d_in[6];
    const float* b3 = (const float*)d_in[7];
    float* out = (float*)d_out;

    int N = in_sizes[0];          // x is [N,1]
    int E = in_sizes[1] / 2;      // edge_index is [2,E]

    int nb = (N + 255) / 256;
    int eb = (E + 255) / 256;
    int pb = ((N * 32) + 255) / 256;   // warp per row

    zero_kernel<<<nb, 256>>>(N);
    detect_kernel<<<1, 32>>>((const unsigned int*)ei);
    hist_kernel<<<eb, 256>>>(ei, E);
    scan_kernel<<<1, 1024>>>(N);
    dinv_kernel<<<nb, 256>>>(N);
    place_kernel<<<eb, 256>>>(ei, E);
    encoder_kernel<<<nb, 256>>>(x, W1, b1, W2, b2, W3, N);

    // K = 10 iterations, ping-pong A<->B; even k: A->B, odd k: B->A; final in A
    for (int k = 0; k < 10; k++)
        prop_kernel<<<pb, 256>>>(k & 1, N);

    final_kernel<<<nb, 256>>>(b3, out, N);
}

// round 2
// speedup vs baseline: 1.2738x; 1.2738x over previous
#include <cuda_runtime.h>

// Problem constants (fixed by the dataset)
#define MAXN 100352
#define MAXE 5000192
#define SCAN_TILE 4096   // 1024 threads * 4 elements

// ---- scratch (static device globals; no allocation allowed) ----
__device__ int   g_count[MAXN];
__device__ int   g_rowptr[MAXN + 1];
__device__ int   g_cursor[MAXN];
__device__ int   g_col[MAXE];
__device__ float g_dinv[MAXN];
__device__ float g_z0[MAXN];
__device__ float g_zA[MAXN], g_zB[MAXN];
__device__ float g_yA[MAXN], g_yB[MAXN];
__device__ int   g_is64;
__device__ int   g_tilesum[64];
__device__ int   g_tileoff[64];

// ---------------------------------------------------------------
// 0) zero counters + detect edge dtype (int64 little-endian -> odd words zero)
__global__ void zero_detect_kernel(const unsigned int* e, int N) {
    int i = blockIdx.x * blockDim.x + threadIdx.x;
    if (i < N) { g_count[i] = 0; g_cursor[i] = 0; }
    if (blockIdx.x == 0 && threadIdx.x == 0) {
        int is64 = 1;
        #pragma unroll 1
        for (int k = 1; k < 1024; k += 2) {
            if (e[k] != 0u) { is64 = 0; break; }
        }
        g_is64 = is64;
    }
}

__device__ __forceinline__ int load_idx(const void* eidx, long long pos) {
    if (g_is64) return (int)((const long long*)eidx)[pos];
    return ((const int*)eidx)[pos];
}

// 1) in-degree histogram over dst
__global__ void hist_kernel(const void* eidx, int E) {
    int e = blockIdx.x * blockDim.x + threadIdx.x;
    if (e >= E) return;
    int d = load_idx(eidx, (long long)E + e);
    atomicAdd(&g_count[d], 1);
}

// ---------------- multi-block exclusive scan of g_count ----------------
// Pass A: per-tile totals (grid = ceil(N/4096), block = 1024, 4 elems/thread)
__global__ void scanA_kernel(int N) {
    __shared__ int wsum[32];
    int t = threadIdx.x;
    int base = blockIdx.x * SCAN_TILE + t * 4;
    int s = 0;
    #pragma unroll
    for (int j = 0; j < 4; j++) {
        int i = base + j;
        if (i < N) s += g_count[i];
    }
    #pragma unroll
    for (int o = 16; o; o >>= 1) s += __shfl_xor_sync(0xffffffffu, s, o);
    if ((t & 31) == 0) wsum[t >> 5] = s;
    __syncthreads();
    if (t < 32) {
        int v = wsum[t];
        #pragma unroll
        for (int o = 16; o; o >>= 1) v += __shfl_xor_sync(0xffffffffu, v, o);
        if (t == 0) g_tilesum[blockIdx.x] = v;
    }
}

// Pass B: exclusive scan of tile sums (tiny; serial on thread 0) + total
__global__ void scanB_kernel(int ntiles, int N) {
    if (threadIdx.x == 0) {
        int acc = 0;
        for (int b = 0; b < ntiles; b++) {
            g_tileoff[b] = acc;
            acc += g_tilesum[b];
        }
        g_rowptr[N] = acc;
    }
}

// Pass C: per-tile exclusive scan -> rowptr, plus dinv = rsqrt(count+1)
__global__ void scanC_kernel(int N) {
    __shared__ int wsum[32];
    int t = threadIdx.x;
    int lane = t & 31;
    int warp = t >> 5;
    int base = blockIdx.x * SCAN_TILE + t * 4;

    int c[4];
    #pragma unroll
    for (int j = 0; j < 4; j++) {
        int i = base + j;
        c[j] = (i < N) ? g_count[i] : 0;
    }
    int local = c[0] + c[1] + c[2] + c[3];

    // inclusive scan of `local` within warp
    int inc = local;
    #pragma unroll
    for (int o = 1; o < 32; o <<= 1) {
        int v = __shfl_up_sync(0xffffffffu, inc, o);
        if (lane >= o) inc += v;
    }
    if (lane == 31) wsum[warp] = inc;
    __syncthreads();
    if (t < 32) {
        int v = wsum[t];
        int iv = v;
        #pragma unroll
        for (int o = 1; o < 32; o <<= 1) {
            int u = __shfl_up_sync(0xffffffffu, iv, o);
            if (lane >= o) iv += u;
        }
        wsum[t] = iv - v;   // exclusive warp offsets
    }
    __syncthreads();
    int off = g_tileoff[blockIdx.x] + wsum[warp] + (inc - local);
    #pragma unroll
    for (int j = 0; j < 4; j++) {
        int i = base + j;
        if (i < N) {
            g_rowptr[i] = off;
            g_dinv[i] = rsqrtf((float)c[j] + 1.0f);
            off += c[j];
        }
    }
}

// 2) CSR placement: col[rowptr[dst] + cursor[dst]++] = src
__global__ void place_kernel(const void* eidx, int E) {
    int e = blockIdx.x * blockDim.x + threadIdx.x;
    if (e >= E) return;
    int s = load_idx(eidx, e);
    int d = load_idx(eidx, (long long)E + e);
    int idx = g_rowptr[d] + atomicAdd(&g_cursor[d], 1);
    g_col[idx] = s;
}

// 3) MLP encoder collapsed to scalar: z0 = relu(relu(x*W1+b1)@W2+b2) @ W3
__global__ void encoder_kernel(const float* __restrict__ x,
                               const float* __restrict__ W1, const float* __restrict__ b1,
                               const float* __restrict__ W2, const float* __restrict__ b2,
                               const float* __restrict__ W3, int N) {
    __shared__ float sW2[256], sW1[16], sb1[16], sb2[16], sW3[16];
    int t = threadIdx.x;
    if (t < 256) sW2[t] = W2[t];
    if (t < 16) { sW1[t] = W1[t]; sb1[t] = b1[t]; sb2[t] = b2[t]; sW3[t] = W3[t]; }
    __syncthreads();
    int i = blockIdx.x * blockDim.x + t;
    if (i >= N) return;
    float xv = x[i];
    float h1[16];
    #pragma unroll
    for (int j = 0; j < 16; j++) h1[j] = fmaxf(xv * sW1[j] + sb1[j], 0.0f);
    float z = 0.0f;
    #pragma unroll
    for (int j = 0; j < 16; j++) {
        float a = sb2[j];
        #pragma unroll
        for (int k = 0; k < 16; k++) a = fmaf(h1[k], sW2[k * 16 + j], a);
        z = fmaf(fmaxf(a, 0.0f), sW3[j], z);
    }
    float di = g_dinv[i];
    g_z0[i] = z;
    g_zA[i] = z;
    g_yA[i] = di * z;   // y = dinv * z
}

// 4) one APPNP step on scalars (warp per row):
//    agg_i = dinv_i * sum_{e in row i} y[col[e]]  +  dinv_i^2 * z_i
//    z'    = 0.9*agg + 0.1*z0 ;  y' = dinv * z'
__global__ void prop_kernel(int flag, int N) {
    const float* __restrict__ yin = flag ? g_yB : g_yA;
    const float* __restrict__ zin = flag ? g_zB : g_zA;
    float* zout = flag ? g_zA : g_zB;
    float* yout = flag ? g_yA : g_yB;

    int gw = (blockIdx.x * blockDim.x + threadIdx.x) >> 5;
    int lane = threadIdx.x & 31;
    if (gw >= N) return;
    int beg = g_rowptr[gw];
    int end = g_rowptr[gw + 1];
    float s = 0.0f;
    for (int e = beg + lane; e < end; e += 32) s += __ldg(&yin[g_col[e]]);
    #pragma unroll
    for (int o = 16; o; o >>= 1) s += __shfl_xor_sync(0xffffffffu, s, o);
    if (lane == 0) {
        float di = g_dinv[gw];
        float agg = fmaf(di, s, di * di * zin[gw]);
        float zn = fmaf(0.9f, agg, 0.1f * g_z0[gw]);
        zout[gw] = zn;
        yout[gw] = di * zn;
    }
}

// 5) out = z_final + b3
__global__ void final_kernel(const float* __restrict__ b3, float* __restrict__ out, int N) {
    int i = blockIdx.x * blockDim.x + threadIdx.x;
    if (i < N) out[i] = g_zA[i] + b3[0];
}

extern "C" void kernel_launch(void* const* d_in, const int* in_sizes, int n_in,
                              void* d_out, int out_size) {
    const float* x  = (const float*)d_in[0];
    const void*  ei = d_in[1];
    const float* W1 = (const float*)d_in[2];
    const float* b1 = (const float*)d_in[3];
    const float* W2 = (const float*)d_in[4];
    const float* b2 = (const float*)d_in[5];
    const float* W3 = (const float*)d_in[6];
    const float* b3 = (const float*)d_in[7];
    float* out = (float*)d_out;

    int N = in_sizes[0];          // x is [N,1]
    int E = in_sizes[1] / 2;      // edge_index is [2,E]

    int nb = (N + 255) / 256;
    int eb = (E + 255) / 256;
    int pb = ((N * 32) + 255) / 256;           // warp per row
    int ntiles = (N + SCAN_TILE - 1) / SCAN_TILE;

    zero_detect_kernel<<<nb, 256>>>((const unsigned int*)ei, N);
    hist_kernel<<<eb, 256>>>(ei, E);
    scanA_kernel<<<ntiles, 1024>>>(N);
    scanB_kernel<<<1, 32>>>(ntiles, N);
    scanC_kernel<<<ntiles, 1024>>>(N);
    place_kernel<<<eb, 256>>>(ei, E);
    encoder_kernel<<<nb, 256>>>(x, W1, b1, W2, b2, W3, N);

    // K = 10 iterations, ping-pong; even k: A->B, odd k: B->A; final in A
    for (int k = 0; k < 10; k++)
        prop_kernel<<<pb, 256>>>(k & 1, N);

    final_kernel<<<nb, 256>>>(b3, out, N);
}